// round 2
// baseline (speedup 1.0000x reference)
#include <cuda_runtime.h>
#include <math.h>

#define MAX_NODES 100000
#define F_DIM 128
#define P_COLS 256   // [PW_src(64) | PA_src(64) | PW_dst(64) | PA_dst(64)]

// Scratch: precomputed per-node projections (static device array — no alloc).
__device__ float g_P[(size_t)MAX_NODES * P_COLS];

// ---------------------------------------------------------------------------
// Kernel 1: P[n, :] = x[n, :] @ B[128, 256]
//   B[:,  0: 64] = W1[  0:128, :]   (src half of W1)
//   B[:, 64:128] = A1[  0:128, :]   (src half of A1)
//   B[:,128:192] = W1[128:256, :]   (dst half of W1)
//   B[:,192:256] = A1[128:256, :]   (dst half of A1)
// Tiled 64x64x64 scalar-fp32 GEMM, 256 threads, 4x4 per thread.
// ---------------------------------------------------------------------------
__global__ void precompute_kernel(const float* __restrict__ x,
                                  const float* __restrict__ W1,
                                  const float* __restrict__ A1,
                                  int n_nodes) {
    __shared__ float Xs[64][65];
    __shared__ float Bs[64][64];

    const int m0 = blockIdx.x * 64;
    const int n0 = blockIdx.y * 64;
    const int tx = threadIdx.x & 15;
    const int ty = threadIdx.x >> 4;

    float acc[4][4] = {};

    for (int k0 = 0; k0 < F_DIM; k0 += 64) {
        // Load X tile (64 nodes x 64 k), zero-pad past n_nodes
        for (int i = threadIdx.x; i < 64 * 64; i += 256) {
            int m = i >> 6, k = i & 63;
            int gm = m0 + m;
            Xs[m][k] = (gm < n_nodes) ? x[(size_t)gm * F_DIM + k0 + k] : 0.f;
        }
        // Load B tile, materializing the [W1top|A1top|W1bot|A1bot] layout on the fly
        for (int i = threadIdx.x; i < 64 * 64; i += 256) {
            int k = i >> 6, n = i & 63;
            int c = n0 + n;          // global column 0..255
            int g = c >> 6;          // which quadrant
            int j = c & 63;
            int krow = k0 + k;
            float v;
            if (g == 0)      v = W1[(size_t)krow * 64 + j];
            else if (g == 1) v = A1[(size_t)krow * 64 + j];
            else if (g == 2) v = W1[(size_t)(128 + krow) * 64 + j];
            else             v = A1[(size_t)(128 + krow) * 64 + j];
            Bs[k][n] = v;
        }
        __syncthreads();

        #pragma unroll
        for (int kk = 0; kk < 64; kk++) {
            float a[4], b[4];
            #pragma unroll
            for (int i = 0; i < 4; i++) a[i] = Xs[ty * 4 + i][kk];
            #pragma unroll
            for (int j = 0; j < 4; j++) b[j] = Bs[kk][tx * 4 + j];
            #pragma unroll
            for (int i = 0; i < 4; i++)
                #pragma unroll
                for (int j = 0; j < 4; j++)
                    acc[i][j] = fmaf(a[i], b[j], acc[i][j]);
        }
        __syncthreads();
    }

    #pragma unroll
    for (int i = 0; i < 4; i++) {
        int gm = m0 + ty * 4 + i;
        if (gm < n_nodes) {
            #pragma unroll
            for (int j = 0; j < 4; j++)
                g_P[(size_t)gm * P_COLS + n0 + tx * 4 + j] = acc[i][j];
        }
    }
}

// ---------------------------------------------------------------------------
// Kernel 2: per-edge residual MLP. One warp per edge, 8 warps / block.
//   layer1: h1[j] = relu(relu(PWs[j]+PWd[j]+b1[j]) + PAs[j]+PAd[j])   (64)
//   layer2: h2[m] = relu(relu(h1@W2 + b2) + h1@A2)                    (32)
//   layer3: h3[m] = relu(relu(h2@W3 + b3) + h2@A3)                    (16)
//   out    = sigmoid(h3@Wf + bf)
// ---------------------------------------------------------------------------
__global__ void edge_kernel(const int* __restrict__ ei,
                            const float* __restrict__ b1,
                            const float* __restrict__ W2, const float* __restrict__ b2,
                            const float* __restrict__ A2,
                            const float* __restrict__ W3, const float* __restrict__ b3,
                            const float* __restrict__ A3,
                            const float* __restrict__ Wf, const float* __restrict__ bf,
                            float* __restrict__ out, int E) {
    __shared__ float W2s[64 * 32], A2s[64 * 32];
    __shared__ float W3s[32 * 16], A3s[32 * 16];
    __shared__ float b1s[64], b2s[32], b3s[16], Wfs[16];
    __shared__ float bfs;
    __shared__ float h1s[8][64];
    __shared__ float h2s[8][32];

    const int tid = threadIdx.x;
    for (int i = tid; i < 64 * 32; i += 256) { W2s[i] = W2[i]; A2s[i] = A2[i]; }
    for (int i = tid; i < 32 * 16; i += 256) { W3s[i] = W3[i]; A3s[i] = A3[i]; }
    if (tid < 64) b1s[tid] = b1[tid];
    if (tid < 32) b2s[tid] = b2[tid];
    if (tid < 16) { b3s[tid] = b3[tid]; Wfs[tid] = Wf[tid]; }
    if (tid == 0) bfs = bf[0];
    __syncthreads();

    const int warp = tid >> 5;
    const int lane = tid & 31;
    const int e = blockIdx.x * 8 + warp;
    if (e >= E) return;

    // Indices as int32 (harness downcasts int64 -> int32). Clamp defensively:
    // if the dtype hypothesis is wrong we want a rel_err signal, not a crash.
    int src = ei[e];
    int dst = ei[(size_t)E + e];
    src = min(max(src, 0), MAX_NODES - 1);
    dst = min(max(dst, 0), MAX_NODES - 1);
    const float* ps = g_P + (size_t)src * P_COLS;        // [PW_s | PA_s]
    const float* pd = g_P + (size_t)dst * P_COLS + 128;  // [PW_d | PA_d]

    // layer 1 (fully factored: gathered adds, coalesced 128B warp loads)
    float w0 = ps[lane]      + pd[lane];
    float w1 = ps[lane + 32] + pd[lane + 32];
    float a0 = ps[64 + lane] + pd[64 + lane];
    float a1 = ps[96 + lane] + pd[96 + lane];
    float h10 = fmaxf(fmaxf(w0 + b1s[lane],      0.f) + a0, 0.f);
    float h11 = fmaxf(fmaxf(w1 + b1s[lane + 32], 0.f) + a1, 0.f);
    h1s[warp][lane]      = h10;
    h1s[warp][lane + 32] = h11;
    __syncwarp();

    // layer 2: lane m computes h2[m]
    float acc = b2s[lane], accA = 0.f;
    #pragma unroll
    for (int j = 0; j < 64; j++) {
        float h = h1s[warp][j];                   // smem broadcast
        acc  = fmaf(h, W2s[j * 32 + lane], acc);  // conflict-free
        accA = fmaf(h, A2s[j * 32 + lane], accA);
    }
    float h2 = fmaxf(fmaxf(acc, 0.f) + accA, 0.f);
    h2s[warp][lane] = h2;
    __syncwarp();

    // layer 3 + head: lanes 0..15 compute h3[m]*Wf[m]; others contribute 0
    float t = 0.f;
    if (lane < 16) {
        float acc3 = b3s[lane], accA3 = 0.f;
        #pragma unroll
        for (int j = 0; j < 32; j++) {
            float h = h2s[warp][j];
            acc3  = fmaf(h, W3s[j * 16 + lane], acc3);
            accA3 = fmaf(h, A3s[j * 16 + lane], accA3);
        }
        float h3 = fmaxf(fmaxf(acc3, 0.f) + accA3, 0.f);
        t = h3 * Wfs[lane];
    }
    #pragma unroll
    for (int o = 8; o > 0; o >>= 1)
        t += __shfl_xor_sync(0xffffffffu, t, o);
    if (lane == 0)
        out[e] = 1.f / (1.f + expf(-(t + bfs)));
}

// ---------------------------------------------------------------------------
// Inputs (metadata order): x, edge_index, W1, b1, A1, W2, b2, A2, W3, b3, A3, Wf, bf
// ---------------------------------------------------------------------------
extern "C" void kernel_launch(void* const* d_in, const int* in_sizes, int n_in,
                              void* d_out, int out_size) {
    const float* x  = (const float*)d_in[0];
    const int*   ei = (const int*)d_in[1];
    const float* W1 = (const float*)d_in[2];
    const float* b1 = (const float*)d_in[3];
    const float* A1 = (const float*)d_in[4];
    const float* W2 = (const float*)d_in[5];
    const float* b2 = (const float*)d_in[6];
    const float* A2 = (const float*)d_in[7];
    const float* W3 = (const float*)d_in[8];
    const float* b3 = (const float*)d_in[9];
    const float* A3 = (const float*)d_in[10];
    const float* Wf = (const float*)d_in[11];
    const float* bf = (const float*)d_in[12];
    float* out = (float*)d_out;

    const int n_nodes = in_sizes[0] / F_DIM;
    const int E = in_sizes[1] / 2;

    dim3 g1((n_nodes + 63) / 64, 4);
    precompute_kernel<<<g1, 256>>>(x, W1, A1, n_nodes);

    const int nb = (E + 7) / 8;
    edge_kernel<<<nb, 256>>>(ei, b1, W2, b2, A2, W3, b3, A3, Wf, bf, out, E);
}

// round 3
// speedup vs baseline: 1.6708x; 1.6708x over previous
#include <cuda_runtime.h>
#include <math.h>

#define MAX_NODES 100000
#define F_DIM 128
#define P_COLS 256   // [PW_src(64) | PA_src(64) | PW_dst(64) | PA_dst(64)]

__device__ float g_P[(size_t)MAX_NODES * P_COLS];

// ---------------- packed f32x2 helpers (sm_103a FFMA2) ----------------
typedef unsigned long long ull;
__device__ __forceinline__ ull pack2(float x, float y) {
    ull r; asm("mov.b64 %0, {%1,%2};" : "=l"(r) : "f"(x), "f"(y)); return r;
}
__device__ __forceinline__ void unpack2(ull v, float& x, float& y) {
    asm("mov.b64 {%0,%1}, %2;" : "=f"(x), "=f"(y) : "l"(v));
}
__device__ __forceinline__ ull fma2(ull a, ull b, ull c) {
    ull d; asm("fma.rn.f32x2 %0, %1, %2, %3;" : "=l"(d) : "l"(a), "l"(b), "l"(c)); return d;
}
__device__ __forceinline__ ull dbits(double d) { return __double_as_longlong(d); }

// ---------------------------------------------------------------------------
// Kernel 1: P[n,:] = x[n,:] @ [W1top | A1top | W1bot | A1bot]  (unchanged)
// ---------------------------------------------------------------------------
__global__ void precompute_kernel(const float* __restrict__ x,
                                  const float* __restrict__ W1,
                                  const float* __restrict__ A1,
                                  int n_nodes) {
    __shared__ float Xs[64][65];
    __shared__ float Bs[64][64];

    const int m0 = blockIdx.x * 64;
    const int n0 = blockIdx.y * 64;
    const int tx = threadIdx.x & 15;
    const int ty = threadIdx.x >> 4;

    float acc[4][4] = {};

    for (int k0 = 0; k0 < F_DIM; k0 += 64) {
        for (int i = threadIdx.x; i < 64 * 64; i += 256) {
            int m = i >> 6, k = i & 63;
            int gm = m0 + m;
            Xs[m][k] = (gm < n_nodes) ? x[(size_t)gm * F_DIM + k0 + k] : 0.f;
        }
        for (int i = threadIdx.x; i < 64 * 64; i += 256) {
            int k = i >> 6, n = i & 63;
            int c = n0 + n;
            int g = c >> 6;
            int j = c & 63;
            int krow = k0 + k;
            float v;
            if (g == 0)      v = W1[(size_t)krow * 64 + j];
            else if (g == 1) v = A1[(size_t)krow * 64 + j];
            else if (g == 2) v = W1[(size_t)(128 + krow) * 64 + j];
            else             v = A1[(size_t)(128 + krow) * 64 + j];
            Bs[k][n] = v;
        }
        __syncthreads();

        #pragma unroll
        for (int kk = 0; kk < 64; kk++) {
            float a[4], b[4];
            #pragma unroll
            for (int i = 0; i < 4; i++) a[i] = Xs[ty * 4 + i][kk];
            #pragma unroll
            for (int j = 0; j < 4; j++) b[j] = Bs[kk][tx * 4 + j];
            #pragma unroll
            for (int i = 0; i < 4; i++)
                #pragma unroll
                for (int j = 0; j < 4; j++)
                    acc[i][j] = fmaf(a[i], b[j], acc[i][j]);
        }
        __syncthreads();
    }

    #pragma unroll
    for (int i = 0; i < 4; i++) {
        int gm = m0 + ty * 4 + i;
        if (gm < n_nodes) {
            #pragma unroll
            for (int j = 0; j < 4; j++)
                g_P[(size_t)gm * P_COLS + n0 + tx * 4 + j] = acc[i][j];
        }
    }
}

// ---------------------------------------------------------------------------
// Kernel 2 (v2): block-tiled. 128 edges per block, 256 threads.
// smem (dynamic, 53.75 KB):
//   sm_h1 : [64][128]  k-major h1 tile                       (8192 floats)
//   sm_X  : union { Wc [64][64] = [W2|A2] ; h2 [32][132] }   (4224 floats)
//   sm_w3 : [32][32] = [W3|A3]                               (1024 floats)
// Stage A: lane-per-edge gather + layer1 -> sm_h1 (k-major)
// Stage B: layer2 GEMM (M=128,N=64,K=64), 8x4 micro-tile, FFMA2
// Stage C: layer3 GEMM (M=128,N=32,K=32) + head + sigmoid
// ---------------------------------------------------------------------------
#define TILE_E 128
#define H1_PITCH 128
#define H2_PITCH 132

__global__ __launch_bounds__(256, 4)
void edge_kernel2(const int* __restrict__ ei,
                  const float* __restrict__ b1,
                  const float* __restrict__ W2, const float* __restrict__ b2,
                  const float* __restrict__ A2,
                  const float* __restrict__ W3, const float* __restrict__ b3,
                  const float* __restrict__ A3,
                  const float* __restrict__ Wf, const float* __restrict__ bf,
                  float* __restrict__ out, int E) {
    extern __shared__ float sm[];
    float* sm_h1 = sm;                  // 8192
    float* sm_X  = sm + 8192;           // 4224 (Wc then h2)
    float* sm_w3 = sm + 8192 + 4224;    // 1024

    const int tid = threadIdx.x;
    const int e_base = blockIdx.x * TILE_E;

    // ---- weight staging (before the sync; sm_X used as Wc = [W2|A2]) ----
    #pragma unroll
    for (int i = 0; i < 16; i++) {
        int idx = tid + i * 256;        // 0..4095
        int k = idx >> 6, n = idx & 63;
        sm_X[k * 64 + n] = (n < 32) ? W2[k * 32 + n] : A2[k * 32 + (n - 32)];
    }
    #pragma unroll
    for (int i = 0; i < 4; i++) {
        int idx = tid + i * 256;        // 0..1023
        int k = idx >> 5, n = idx & 31;
        sm_w3[k * 32 + n] = (n < 16) ? W3[k * 16 + n] : A3[k * 16 + (n - 16)];
    }

    // ---- Stage A: gather + layer1 ----
    {
        const int e_l = tid & 127;      // edge within tile
        const int half = tid >> 7;      // 0: chunks 0..7 (j 0..31), 1: chunks 8..15
        const int eg = e_base + e_l;
        const bool e_ok = (eg < E);
        int src = e_ok ? ei[eg] : 0;
        int dst = e_ok ? ei[(size_t)E + eg] : 0;
        src = min(max(src, 0), MAX_NODES - 1);
        dst = min(max(dst, 0), MAX_NODES - 1);
        const float* ps = g_P + (size_t)src * P_COLS;        // [PW_s | PA_s]
        const float* pd = g_P + (size_t)dst * P_COLS + 128;  // [PW_d | PA_d]

        #pragma unroll
        for (int cc = 0; cc < 8; cc++) {
            const int c = half * 8 + cc;   // chunk: j = 4c..4c+3
            const int j0 = 4 * c;
            float4 pw = *(const float4*)(ps + j0);
            float4 dw = *(const float4*)(pd + j0);
            float4 pa = *(const float4*)(ps + 64 + j0);
            float4 da = *(const float4*)(pd + 64 + j0);
            float h0 = fmaxf(fmaxf(pw.x + dw.x + __ldg(b1 + j0 + 0), 0.f) + pa.x + da.x, 0.f);
            float h1v = fmaxf(fmaxf(pw.y + dw.y + __ldg(b1 + j0 + 1), 0.f) + pa.y + da.y, 0.f);
            float h2v = fmaxf(fmaxf(pw.z + dw.z + __ldg(b1 + j0 + 2), 0.f) + pa.z + da.z, 0.f);
            float h3v = fmaxf(fmaxf(pw.w + dw.w + __ldg(b1 + j0 + 3), 0.f) + pa.w + da.w, 0.f);
            sm_h1[(j0 + 0) * H1_PITCH + e_l] = h0;
            sm_h1[(j0 + 1) * H1_PITCH + e_l] = h1v;
            sm_h1[(j0 + 2) * H1_PITCH + e_l] = h2v;
            sm_h1[(j0 + 3) * H1_PITCH + e_l] = h3v;
        }
    }
    __syncthreads();

    // ---- Stage B: layer2 GEMM, out[128][64] ([W2 cols | A2 cols]) ----
    const int tx = tid & 15;
    const int ty = tid >> 4;
    const int m0 = ty * 8;
    const int n0 = tx * 4;

    ull acc[4][4];
    #pragma unroll
    for (int ip = 0; ip < 4; ip++)
        #pragma unroll
        for (int c = 0; c < 4; c++) acc[ip][c] = 0ull;

    #pragma unroll
    for (int k = 0; k < 64; k++) {
        const double2 A0 = *(const double2*)(sm_h1 + k * H1_PITCH + m0);
        const double2 A1 = *(const double2*)(sm_h1 + k * H1_PITCH + m0 + 4);
        const float4 b = *(const float4*)(sm_X + k * 64 + n0);
        ull ar[4] = { dbits(A0.x), dbits(A0.y), dbits(A1.x), dbits(A1.y) };
        ull bd[4] = { pack2(b.x, b.x), pack2(b.y, b.y), pack2(b.z, b.z), pack2(b.w, b.w) };
        #pragma unroll
        for (int ip = 0; ip < 4; ip++)
            #pragma unroll
            for (int c = 0; c < 4; c++)
                acc[ip][c] = fma2(ar[ip], bd[c], acc[ip][c]);
    }
    __syncthreads();  // everyone done reading Wc before h2 overwrites sm_X

    // combine W/A halves: lane tx<8 holds W cols n0..n0+3; A part at lane+8
    #pragma unroll
    for (int ip = 0; ip < 4; ip++) {
        #pragma unroll
        for (int c = 0; c < 4; c++) {
            ull other = __shfl_down_sync(0xffffffffu, acc[ip][c], 8);
            if (tx < 8) {
                float wlo, whi, alo, ahi;
                unpack2(acc[ip][c], wlo, whi);
                unpack2(other, alo, ahi);
                float bb = __ldg(b2 + n0 + c);
                float v0 = fmaxf(fmaxf(wlo + bb, 0.f) + alo, 0.f);
                float v1 = fmaxf(fmaxf(whi + bb, 0.f) + ahi, 0.f);
                sm_X[(n0 + c) * H2_PITCH + m0 + 2 * ip]     = v0;
                sm_X[(n0 + c) * H2_PITCH + m0 + 2 * ip + 1] = v1;
            }
        }
    }
    __syncthreads();

    // ---- Stage C: layer3 GEMM out[128][32] ([W3 | A3]) + head ----
    const int n0c = tx * 2;
    ull acc3[4][2];
    #pragma unroll
    for (int ip = 0; ip < 4; ip++) { acc3[ip][0] = 0ull; acc3[ip][1] = 0ull; }

    #pragma unroll
    for (int k = 0; k < 32; k++) {
        const double2 A0 = *(const double2*)(sm_X + k * H2_PITCH + m0);
        const double2 A1 = *(const double2*)(sm_X + k * H2_PITCH + m0 + 4);
        const float2 b = *(const float2*)(sm_w3 + k * 32 + n0c);
        ull ar[4] = { dbits(A0.x), dbits(A0.y), dbits(A1.x), dbits(A1.y) };
        ull bd0 = pack2(b.x, b.x);
        ull bd1 = pack2(b.y, b.y);
        #pragma unroll
        for (int ip = 0; ip < 4; ip++) {
            acc3[ip][0] = fma2(ar[ip], bd0, acc3[ip][0]);
            acc3[ip][1] = fma2(ar[ip], bd1, acc3[ip][1]);
        }
    }

    float p[8];
    #pragma unroll
    for (int i = 0; i < 8; i++) p[i] = 0.f;

    #pragma unroll
    for (int ip = 0; ip < 4; ip++) {
        #pragma unroll
        for (int c = 0; c < 2; c++) {
            ull other = __shfl_down_sync(0xffffffffu, acc3[ip][c], 8);
            if (tx < 8) {
                float wlo, whi, alo, ahi;
                unpack2(acc3[ip][c], wlo, whi);
                unpack2(other, alo, ahi);
                int n = n0c + c;                 // 0..15
                float bb = __ldg(b3 + n);
                float wf = __ldg(Wf + n);
                float h3lo = fmaxf(fmaxf(wlo + bb, 0.f) + alo, 0.f);
                float h3hi = fmaxf(fmaxf(whi + bb, 0.f) + ahi, 0.f);
                p[2 * ip]     += h3lo * wf;
                p[2 * ip + 1] += h3hi * wf;
            }
        }
    }

    // reduce partial head sums across tx=0..7 (lanes 0..7 / 16..23)
    #pragma unroll
    for (int o = 1; o < 8; o <<= 1) {
        #pragma unroll
        for (int i = 0; i < 8; i++)
            p[i] += __shfl_xor_sync(0xffffffffu, p[i], o);
    }

    if (tx == 0) {
        float bfv = __ldg(bf);
        #pragma unroll
        for (int i = 0; i < 8; i++) {
            int eg = e_base + m0 + i;
            if (eg < E) out[eg] = 1.f / (1.f + expf(-(p[i] + bfv)));
        }
    }
}

// ---------------------------------------------------------------------------
extern "C" void kernel_launch(void* const* d_in, const int* in_sizes, int n_in,
                              void* d_out, int out_size) {
    const float* x  = (const float*)d_in[0];
    const int*   ei = (const int*)d_in[1];
    const float* W1 = (const float*)d_in[2];
    const float* b1 = (const float*)d_in[3];
    const float* A1 = (const float*)d_in[4];
    const float* W2 = (const float*)d_in[5];
    const float* b2 = (const float*)d_in[6];
    const float* A2 = (const float*)d_in[7];
    const float* W3 = (const float*)d_in[8];
    const float* b3 = (const float*)d_in[9];
    const float* A3 = (const float*)d_in[10];
    const float* Wf = (const float*)d_in[11];
    const float* bf = (const float*)d_in[12];
    float* out = (float*)d_out;

    const int n_nodes = in_sizes[0] / F_DIM;
    const int E = in_sizes[1] / 2;

    dim3 g1((n_nodes + 63) / 64, 4);
    precompute_kernel<<<g1, 256>>>(x, W1, A1, n_nodes);

    const int smem_bytes = (8192 + 4224 + 1024) * 4;   // 53760
    cudaFuncSetAttribute(edge_kernel2, cudaFuncAttributeMaxDynamicSharedMemorySize, smem_bytes);
    const int nb = (E + TILE_E - 1) / TILE_E;
    edge_kernel2<<<nb, 256, smem_bytes>>>(ei, b1, W2, b2, A2, W3, b3, A3, Wf, bf, out, E);
}

// round 4
// speedup vs baseline: 2.9302x; 1.7538x over previous
#include <cuda_runtime.h>
#include <math.h>

#define MAX_NODES 100000
#define F_DIM 128
#define P_COLS 256   // [PW_src(64) | PA_src(64) | PW_dst(64) | PA_dst(64)]

__device__ float g_P[(size_t)MAX_NODES * P_COLS];

// ---------------- packed f32x2 helpers (sm_103a FFMA2) ----------------
typedef unsigned long long ull;
__device__ __forceinline__ ull pack2(float x, float y) {
    ull r; asm("mov.b64 %0, {%1,%2};" : "=l"(r) : "f"(x), "f"(y)); return r;
}
__device__ __forceinline__ void unpack2(ull v, float& x, float& y) {
    asm("mov.b64 {%0,%1}, %2;" : "=f"(x), "=f"(y) : "l"(v));
}
__device__ __forceinline__ ull fma2(ull a, ull b, ull c) {
    ull d; asm("fma.rn.f32x2 %0, %1, %2, %3;" : "=l"(d) : "l"(a), "l"(b), "l"(c)); return d;
}
__device__ __forceinline__ ull dbits(double d) { return __double_as_longlong(d); }

// ---------------------------------------------------------------------------
// Kernel 1 (v2): P[n,:] = x[n,:] @ [W1top | A1top | W1bot | A1bot]
// k-major Xs + FFMA2 m-paired accumulators. 64x64 tile, 256 thr, 4x4/thread.
// ---------------------------------------------------------------------------
#define XS_PITCH 68
__global__ __launch_bounds__(256, 4)
void precompute_kernel(const float* __restrict__ x,
                       const float* __restrict__ W1,
                       const float* __restrict__ A1,
                       int n_nodes) {
    __shared__ float Xs[64 * XS_PITCH];   // [k][m], pitch 68
    __shared__ float Bs[64 * 64];         // [k][n]

    const int tid = threadIdx.x;
    const int m0b = blockIdx.x * 64;
    const int n0b = blockIdx.y * 64;
    const int tx = tid & 15;
    const int ty = tid >> 4;
    const int m0 = ty * 4;
    const int n0 = tx * 4;

    ull acc[2][4];
    #pragma unroll
    for (int i = 0; i < 2; i++)
        #pragma unroll
        for (int j = 0; j < 4; j++) acc[i][j] = 0ull;

    for (int k0 = 0; k0 < F_DIM; k0 += 64) {
        // X tile -> k-major smem
        for (int i = tid; i < 64 * 64; i += 256) {
            int m = i >> 6, k = i & 63;
            int gm = m0b + m;
            Xs[k * XS_PITCH + m] = (gm < n_nodes) ? x[(size_t)gm * F_DIM + k0 + k] : 0.f;
        }
        // B tile ([W1top|A1top|W1bot|A1bot] materialized on the fly)
        for (int i = tid; i < 64 * 64; i += 256) {
            int k = i >> 6, n = i & 63;
            int c = n0b + n;
            int g = c >> 6;
            int j = c & 63;
            int krow = k0 + k;
            float v;
            if (g == 0)      v = W1[(size_t)krow * 64 + j];
            else if (g == 1) v = A1[(size_t)krow * 64 + j];
            else if (g == 2) v = W1[(size_t)(128 + krow) * 64 + j];
            else             v = A1[(size_t)(128 + krow) * 64 + j];
            Bs[k * 64 + n] = v;
        }
        __syncthreads();

        #pragma unroll
        for (int kk = 0; kk < 64; kk++) {
            const double2 av = *(const double2*)(Xs + kk * XS_PITCH + m0);
            const float4  bv = *(const float4*)(Bs + kk * 64 + n0);
            ull a0 = dbits(av.x), a1 = dbits(av.y);
            ull bd[4] = { pack2(bv.x, bv.x), pack2(bv.y, bv.y),
                          pack2(bv.z, bv.z), pack2(bv.w, bv.w) };
            #pragma unroll
            for (int j = 0; j < 4; j++) {
                acc[0][j] = fma2(a0, bd[j], acc[0][j]);
                acc[1][j] = fma2(a1, bd[j], acc[1][j]);
            }
        }
        __syncthreads();
    }

    #pragma unroll
    for (int i = 0; i < 2; i++) {
        float r0[4], r1[4];
        #pragma unroll
        for (int j = 0; j < 4; j++) unpack2(acc[i][j], r0[j], r1[j]);
        int gm0 = m0b + m0 + 2 * i;
        if (gm0 < n_nodes)
            *(float4*)(&g_P[(size_t)gm0 * P_COLS + n0b + n0]) = make_float4(r0[0], r0[1], r0[2], r0[3]);
        if (gm0 + 1 < n_nodes)
            *(float4*)(&g_P[(size_t)(gm0 + 1) * P_COLS + n0b + n0]) = make_float4(r1[0], r1[1], r1[2], r1[3]);
    }
}

// ---------------------------------------------------------------------------
// Kernel 2 (v3): 128 edges/block, 256 threads.
// Stage A: warp-per-edge COALESCED gather (2 edges/iter via half-warps),
//          XOR-swizzled k-major h1 store (2-way max conflicts).
// Stage B: layer2 GEMM (M=128,N=64,K=64), 8x4 micro-tile, FFMA2,
//          swizzle-aware broadcast A loads.
// Stage C: layer3 GEMM + head + sigmoid (unchanged from v2).
// ---------------------------------------------------------------------------
#define TILE_E 128
#define H1_PITCH 128
#define H2_PITCH 132

// swizzled physical offset of h1[j][e] within the [64][128] tile
__device__ __forceinline__ int h1_swz(int j, int e) {
    return j * H1_PITCH + ((((e >> 2) ^ ((j >> 2) & 7))) << 2) + (e & 3);
}

__global__ __launch_bounds__(256, 4)
void edge_kernel3(const int* __restrict__ ei,
                  const float* __restrict__ b1,
                  const float* __restrict__ W2, const float* __restrict__ b2,
                  const float* __restrict__ A2,
                  const float* __restrict__ W3, const float* __restrict__ b3,
                  const float* __restrict__ A3,
                  const float* __restrict__ Wf, const float* __restrict__ bf,
                  float* __restrict__ out, int E) {
    extern __shared__ float sm[];
    float* sm_h1 = sm;                  // 8192 floats (swizzled k-major)
    float* sm_X  = sm + 8192;           // 4224 (Wc [64][64], then h2 [32][132])
    float* sm_w3 = sm + 8192 + 4224;    // 1024 ([W3|A3] [32][32])

    const int tid = threadIdx.x;
    const int e_base = blockIdx.x * TILE_E;
    const int warp = tid >> 5;
    const int lane = tid & 31;

    // ---- weight staging ----
    #pragma unroll
    for (int i = 0; i < 16; i++) {
        int idx = tid + i * 256;
        int k = idx >> 6, n = idx & 63;
        sm_X[k * 64 + n] = (n < 32) ? W2[k * 32 + n] : A2[k * 32 + (n - 32)];
    }
    #pragma unroll
    for (int i = 0; i < 4; i++) {
        int idx = tid + i * 256;
        int k = idx >> 5, n = idx & 31;
        sm_w3[k * 32 + n] = (n < 16) ? W3[k * 16 + n] : A3[k * 16 + (n - 16)];
    }

    // ---- Stage A: coalesced gather + layer1, 16 edges per warp ----
    {
        const int e0 = e_base + warp * 16;
        // lanes 0-15 hold src of local edges 0..15; lanes 16-31 hold dst
        int myidx = 0;
        {
            int el = lane & 15;
            int eg = e0 + el;
            if (eg < E) myidx = (lane < 16) ? ei[eg] : ei[(size_t)E + eg];
            myidx = min(max(myidx, 0), MAX_NODES - 1);
        }
        const int l15 = lane & 15;
        const float4 b1v = *(const float4*)(b1 + 4 * l15);
        const int j0 = 4 * l15;
        const int xg = l15 & 7;   // (j>>2)&7 for this lane's rows

        #pragma unroll
        for (int p = 0; p < 8; p++) {
            const int srcA = __shfl_sync(0xffffffffu, myidx, 2 * p);
            const int dstA = __shfl_sync(0xffffffffu, myidx, 16 + 2 * p);
            const int srcB = __shfl_sync(0xffffffffu, myidx, 2 * p + 1);
            const int dstB = __shfl_sync(0xffffffffu, myidx, 17 + 2 * p);

            // full 128-float half-rows, coalesced: lane*4 within row
            const float4 sA = *(const float4*)(g_P + (size_t)srcA * P_COLS + lane * 4);
            const float4 dA = *(const float4*)(g_P + (size_t)dstA * P_COLS + 128 + lane * 4);
            const float4 sB = *(const float4*)(g_P + (size_t)srcB * P_COLS + lane * 4);
            const float4 dB = *(const float4*)(g_P + (size_t)dstB * P_COLS + 128 + lane * 4);

            float4 wA, wB;
            wA.x = sA.x + dA.x; wA.y = sA.y + dA.y; wA.z = sA.z + dA.z; wA.w = sA.w + dA.w;
            wB.x = sB.x + dB.x; wB.y = sB.y + dB.y; wB.z = sB.z + dB.z; wB.w = sB.w + dB.w;

            // lanes<16: need A-part of edge A (lives in lanes 16-31 of wA)
            // lanes>=16: need W-part of edge B (lives in lanes 0-15 of wB)
            float4 oA, oB;
            oA.x = __shfl_xor_sync(0xffffffffu, wA.x, 16);
            oA.y = __shfl_xor_sync(0xffffffffu, wA.y, 16);
            oA.z = __shfl_xor_sync(0xffffffffu, wA.z, 16);
            oA.w = __shfl_xor_sync(0xffffffffu, wA.w, 16);
            oB.x = __shfl_xor_sync(0xffffffffu, wB.x, 16);
            oB.y = __shfl_xor_sync(0xffffffffu, wB.y, 16);
            oB.z = __shfl_xor_sync(0xffffffffu, wB.z, 16);
            oB.w = __shfl_xor_sync(0xffffffffu, wB.w, 16);

            const bool lo = (lane < 16);
            float4 w, a;
            w.x = lo ? wA.x : oB.x;  a.x = lo ? oA.x : wB.x;
            w.y = lo ? wA.y : oB.y;  a.y = lo ? oA.y : wB.y;
            w.z = lo ? wA.z : oB.z;  a.z = lo ? oA.z : wB.z;
            w.w = lo ? wA.w : oB.w;  a.w = lo ? oA.w : wB.w;

            float h0 = fmaxf(fmaxf(w.x + b1v.x, 0.f) + a.x, 0.f);
            float h1v = fmaxf(fmaxf(w.y + b1v.y, 0.f) + a.y, 0.f);
            float h2v = fmaxf(fmaxf(w.z + b1v.z, 0.f) + a.z, 0.f);
            float h3v = fmaxf(fmaxf(w.w + b1v.w, 0.f) + a.w, 0.f);

            const int e_loc = warp * 16 + 2 * p + (lo ? 0 : 1);
            const int base = j0 * H1_PITCH + ((((e_loc >> 2) ^ xg)) << 2) + (e_loc & 3);
            sm_h1[base]                = h0;   // rows j0..j0+3 share (j>>2), so same swizzle
            sm_h1[base + H1_PITCH]     = h1v;
            sm_h1[base + 2 * H1_PITCH] = h2v;
            sm_h1[base + 3 * H1_PITCH] = h3v;
        }
    }
    __syncthreads();

    // ---- Stage B: layer2 GEMM, out[128][64] ([W2 cols | A2 cols]) ----
    const int tx = tid & 15;
    const int ty = tid >> 4;
    const int m0 = ty * 8;
    const int n0 = tx * 4;
    const int g0 = 2 * ty;      // group index of m0..m0+3
    const int g1 = 2 * ty + 1;  // group index of m0+4..m0+7

    ull acc[4][4];
    #pragma unroll
    for (int ip = 0; ip < 4; ip++)
        #pragma unroll
        for (int c = 0; c < 4; c++) acc[ip][c] = 0ull;

    #pragma unroll
    for (int k = 0; k < 64; k++) {
        const int xr = (k >> 2) & 7;
        const double2 A0 = *(const double2*)(sm_h1 + k * H1_PITCH + ((g0 ^ xr) << 2));
        const double2 A1 = *(const double2*)(sm_h1 + k * H1_PITCH + ((g1 ^ xr) << 2));
        const float4 b = *(const float4*)(sm_X + k * 64 + n0);
        ull ar[4] = { dbits(A0.x), dbits(A0.y), dbits(A1.x), dbits(A1.y) };
        ull bd[4] = { pack2(b.x, b.x), pack2(b.y, b.y), pack2(b.z, b.z), pack2(b.w, b.w) };
        #pragma unroll
        for (int ip = 0; ip < 4; ip++)
            #pragma unroll
            for (int c = 0; c < 4; c++)
                acc[ip][c] = fma2(ar[ip], bd[c], acc[ip][c]);
    }
    __syncthreads();  // everyone done reading Wc before h2 overwrites sm_X

    // combine W/A halves: lane tx<8 holds W cols n0..n0+3; A part at lane+8
    #pragma unroll
    for (int ip = 0; ip < 4; ip++) {
        #pragma unroll
        for (int c = 0; c < 4; c++) {
            ull other = __shfl_down_sync(0xffffffffu, acc[ip][c], 8);
            if (tx < 8) {
                float wlo, whi, alo, ahi;
                unpack2(acc[ip][c], wlo, whi);
                unpack2(other, alo, ahi);
                float bb = __ldg(b2 + n0 + c);
                float v0 = fmaxf(fmaxf(wlo + bb, 0.f) + alo, 0.f);
                float v1 = fmaxf(fmaxf(whi + bb, 0.f) + ahi, 0.f);
                sm_X[(n0 + c) * H2_PITCH + m0 + 2 * ip]     = v0;
                sm_X[(n0 + c) * H2_PITCH + m0 + 2 * ip + 1] = v1;
            }
        }
    }
    __syncwarp();   // h2 producer/consumer is warp-local (warp = 2 ty x 16 tx)

    // ---- Stage C: layer3 GEMM out[128][32] ([W3 | A3]) + head ----
    const int n0c = tx * 2;
    ull acc3[4][2];
    #pragma unroll
    for (int ip = 0; ip < 4; ip++) { acc3[ip][0] = 0ull; acc3[ip][1] = 0ull; }

    #pragma unroll
    for (int k = 0; k < 32; k++) {
        const double2 A0 = *(const double2*)(sm_X + k * H2_PITCH + m0);
        const double2 A1 = *(const double2*)(sm_X + k * H2_PITCH + m0 + 4);
        const float2 b = *(const float2*)(sm_w3 + k * 32 + n0c);
        ull ar[4] = { dbits(A0.x), dbits(A0.y), dbits(A1.x), dbits(A1.y) };
        ull bd0 = pack2(b.x, b.x);
        ull bd1 = pack2(b.y, b.y);
        #pragma unroll
        for (int ip = 0; ip < 4; ip++) {
            acc3[ip][0] = fma2(ar[ip], bd0, acc3[ip][0]);
            acc3[ip][1] = fma2(ar[ip], bd1, acc3[ip][1]);
        }
    }

    float p[8];
    #pragma unroll
    for (int i = 0; i < 8; i++) p[i] = 0.f;

    #pragma unroll
    for (int ip = 0; ip < 4; ip++) {
        #pragma unroll
        for (int c = 0; c < 2; c++) {
            ull other = __shfl_down_sync(0xffffffffu, acc3[ip][c], 8);
            if (tx < 8) {
                float wlo, whi, alo, ahi;
                unpack2(acc3[ip][c], wlo, whi);
                unpack2(other, alo, ahi);
                int n = n0c + c;
                float bb = __ldg(b3 + n);
                float wf = __ldg(Wf + n);
                float h3lo = fmaxf(fmaxf(wlo + bb, 0.f) + alo, 0.f);
                float h3hi = fmaxf(fmaxf(whi + bb, 0.f) + ahi, 0.f);
                p[2 * ip]     += h3lo * wf;
                p[2 * ip + 1] += h3hi * wf;
            }
        }
    }

    #pragma unroll
    for (int o = 1; o < 8; o <<= 1) {
        #pragma unroll
        for (int i = 0; i < 8; i++)
            p[i] += __shfl_xor_sync(0xffffffffu, p[i], o);
    }

    if (tx == 0) {
        float bfv = __ldg(bf);
        #pragma unroll
        for (int i = 0; i < 8; i++) {
            int eg = e_base + m0 + i;
            if (eg < E) out[eg] = 1.f / (1.f + expf(-(p[i] + bfv)));
        }
    }
}

// ---------------------------------------------------------------------------
extern "C" void kernel_launch(void* const* d_in, const int* in_sizes, int n_in,
                              void* d_out, int out_size) {
    const float* x  = (const float*)d_in[0];
    const int*   ei = (const int*)d_in[1];
    const float* W1 = (const float*)d_in[2];
    const float* b1 = (const float*)d_in[3];
    const float* A1 = (const float*)d_in[4];
    const float* W2 = (const float*)d_in[5];
    const float* b2 = (const float*)d_in[6];
    const float* A2 = (const float*)d_in[7];
    const float* W3 = (const float*)d_in[8];
    const float* b3 = (const float*)d_in[9];
    const float* A3 = (const float*)d_in[10];
    const float* Wf = (const float*)d_in[11];
    const float* bf = (const float*)d_in[12];
    float* out = (float*)d_out;

    const int n_nodes = in_sizes[0] / F_DIM;
    const int E = in_sizes[1] / 2;

    dim3 g1((n_nodes + 63) / 64, 4);
    precompute_kernel<<<g1, 256>>>(x, W1, A1, n_nodes);

    const int smem_bytes = (8192 + 4224 + 1024) * 4;   // 53760
    cudaFuncSetAttribute(edge_kernel3, cudaFuncAttributeMaxDynamicSharedMemorySize, smem_bytes);
    const int nb = (E + TILE_E - 1) / TILE_E;
    edge_kernel3<<<nb, 256, smem_bytes>>>(ei, b1, W2, b2, A2, W3, b3, A3, Wf, bf, out, E);
}